// round 1
// baseline (speedup 1.0000x reference)
#include <cuda_runtime.h>
#include <cuda_bf16.h>
#include <math.h>

#define MAXN 50000
#define MAXE 800000

// ---------------- scratch (device globals; no allocation allowed) ----------------
__device__ int   g_is64;
__device__ int   g_src[MAXE];
__device__ int   g_dst[MAXE];
__device__ int   g_rowptr[MAXN + 1];
__device__ int   g_cursor[MAXN];
__device__ int   g_elist[MAXE];
__device__ __align__(16) float g_h1[MAXN * 64];
__device__ __align__(16) float g_xl2[(size_t)MAXN * 128];
__device__ __align__(16) float g_xr2[(size_t)MAXN * 128];
__device__ float g_p[MAXN];
__device__ float g_q[MAXN];
// layer-1 folded constants: float4(cS, cD, cE, cC) per channel j (j = h*8+c)
__device__ __align__(16) float4 g_cpack[64];
__device__ float g_aggA[64];   // = W0@Wl1 (source-side coefficient)
__device__ float g_aggC[64];   // = b0@Wl1 + bl1 (source-side constant)
// layer-2 folded edge-embedding: ee2 = a*u2 + v2
__device__ float g_u2[128];
__device__ float g_v2[128];

// ---------------- tiny precompute + int64 detection ----------------
__global__ void k_pre(const float* __restrict__ W_em, const float* __restrict__ b_em,
                      const float* __restrict__ W0,   const float* __restrict__ b0,
                      const float* __restrict__ Wl1,  const float* __restrict__ bl1,
                      const float* __restrict__ Wr1,  const float* __restrict__ br1,
                      const float* __restrict__ We1,  const float* __restrict__ We2,
                      const void* __restrict__ ei)
{
    int t = threadIdx.x;
    if (t == 0) {
        // int64 values are node ids < 2^31; int32 pairs read as int64 are >= 2^32 whp
        const long long* p = (const long long*)ei;
        int is64 = 1;
        for (int i = 0; i < 8; i++) {
            long long v = p[i];
            if (v < 0 || v >= (1LL << 31)) { is64 = 0; break; }
        }
        g_is64 = is64;
    }
    if (t < 64) {
        float cS = 0.f, cD = 0.f, cE = 0.f;
        float Cl = bl1[t], Cr = br1[t], v1 = 0.f;
        for (int k = 0; k < 128; k++) {
            float wl = Wl1[k * 64 + t];
            float wr = Wr1[k * 64 + t];
            float we = We1[k * 64 + t];
            cS += W0[k]   * wl;
            cD += W0[k]   * wr;
            cE += W_em[k] * we;
            Cl += b0[k]   * wl;
            Cr += b0[k]   * wr;
            v1 += b_em[k] * we;
        }
        g_cpack[t] = make_float4(cS, cD, cE, Cl + Cr + v1);
        g_aggA[t] = cS;
        g_aggC[t] = Cl;
    }
    if (t < 128) {
        float u = 0.f, v = 0.f;
        for (int k = 0; k < 128; k++) {
            float w = We2[k * 128 + t];
            u += W_em[k] * w;
            v += b_em[k] * w;
        }
        g_u2[t] = u;
        g_v2[t] = v;
    }
}

// ---------------- CSR build ----------------
__global__ void k_zero(int n) {
    int i = blockIdx.x * blockDim.x + threadIdx.x;
    if (i < n) g_cursor[i] = 0;
}

__global__ void k_convert(const void* __restrict__ ei, int E) {
    int e = blockIdx.x * blockDim.x + threadIdx.x;
    if (e >= E) return;
    int s, d;
    if (g_is64) {
        const long long* p = (const long long*)ei;
        s = (int)p[e]; d = (int)p[E + e];
    } else {
        const int* p = (const int*)ei;
        s = p[e]; d = p[E + e];
    }
    g_src[e] = s;
    g_dst[e] = d;
    atomicAdd(&g_cursor[d], 1);
}

// single-block exclusive scan of g_cursor[0..n) into g_rowptr[0..n]
__global__ void k_scan(int n) {
    __shared__ int swsum[32];
    __shared__ int s_carry;
    int tid = threadIdx.x;
    int lane = tid & 31, w = tid >> 5;
    if (tid == 0) s_carry = 0;
    __syncthreads();
    for (int base = 0; base < n; base += 1024) {
        int i = base + tid;
        int v = (i < n) ? g_cursor[i] : 0;
        int xv = v;
        #pragma unroll
        for (int off = 1; off < 32; off <<= 1) {
            int t = __shfl_up_sync(0xffffffffu, xv, off);
            if (lane >= off) xv += t;
        }
        if (lane == 31) swsum[w] = xv;
        __syncthreads();
        if (w == 0) {
            int y = swsum[lane];
            #pragma unroll
            for (int off = 1; off < 32; off <<= 1) {
                int t = __shfl_up_sync(0xffffffffu, y, off);
                if (lane >= off) y += t;
            }
            swsum[lane] = y;
        }
        __syncthreads();
        int incl = xv + (w > 0 ? swsum[w - 1] : 0);
        int carry = s_carry;
        if (i < n) g_rowptr[i] = carry + incl - v;
        __syncthreads();
        if (tid == 1023) s_carry = carry + swsum[31];
        __syncthreads();
    }
    if (tid == 0) g_rowptr[n] = s_carry;
}

__global__ void k_scatter(int E) {
    int e = blockIdx.x * blockDim.x + threadIdx.x;
    if (e >= E) return;
    int d = g_dst[e];
    int pos = atomicAdd(&g_cursor[d], 1);
    g_elist[g_rowptr[d] + pos] = e;
}

// ---------------- layer 1: warp per dst node ----------------
__global__ void k_layer1(const float* __restrict__ x, const float* __restrict__ ea,
                         const float* __restrict__ att1, const float* __restrict__ bias1,
                         int N)
{
    __shared__ float4 sc[64];
    __shared__ float  sa[64];
    int tid = threadIdx.x;
    if (tid < 64) { sc[tid] = g_cpack[tid]; sa[tid] = att1[tid]; }
    __syncthreads();
    int warp = tid >> 5, lane = tid & 31;
    int n = blockIdx.x * 8 + warp;
    if (n >= N) return;
    int beg = g_rowptr[n], end = g_rowptr[n + 1];
    float xd = x[n];

    float mx[8], den[8], s1[8];
    #pragma unroll
    for (int h = 0; h < 8; h++) { mx[h] = -1e30f; den[h] = 0.f; s1[h] = 0.f; }

    // pass 1: per-head running max
    for (int ei = beg + lane; ei < end; ei += 32) {
        int e = g_elist[ei];
        float xs = x[g_src[e]];
        float a  = ea[e];
        #pragma unroll
        for (int h = 0; h < 8; h++) {
            float scv = 0.f;
            #pragma unroll
            for (int c = 0; c < 8; c++) {
                int j = h * 8 + c;
                float4 q = sc[j];
                float m = fmaf(q.x, xs, fmaf(q.y, xd, fmaf(q.z, a, q.w)));
                m = m > 0.f ? m : 0.2f * m;
                scv = fmaf(m, sa[j], scv);
            }
            mx[h] = fmaxf(mx[h], scv);
        }
    }
    #pragma unroll
    for (int h = 0; h < 8; h++)
        #pragma unroll
        for (int off = 16; off; off >>= 1)
            mx[h] = fmaxf(mx[h], __shfl_xor_sync(0xffffffffu, mx[h], off));

    // pass 2: exp-sum and weighted sum of x[src]
    for (int ei = beg + lane; ei < end; ei += 32) {
        int e = g_elist[ei];
        float xs = x[g_src[e]];
        float a  = ea[e];
        #pragma unroll
        for (int h = 0; h < 8; h++) {
            float scv = 0.f;
            #pragma unroll
            for (int c = 0; c < 8; c++) {
                int j = h * 8 + c;
                float4 q = sc[j];
                float m = fmaf(q.x, xs, fmaf(q.y, xd, fmaf(q.z, a, q.w)));
                m = m > 0.f ? m : 0.2f * m;
                scv = fmaf(m, sa[j], scv);
            }
            float ex = __expf(scv - mx[h]);
            den[h] += ex;
            s1[h]  = fmaf(ex, xs, s1[h]);
        }
    }
    #pragma unroll
    for (int h = 0; h < 8; h++)
        #pragma unroll
        for (int off = 16; off; off >>= 1) {
            den[h] += __shfl_xor_sync(0xffffffffu, den[h], off);
            s1[h]  += __shfl_xor_sync(0xffffffffu, s1[h],  off);
        }

    float s0 = (end > beg) ? 1.f : 0.f;
    #pragma unroll
    for (int r = 0; r < 2; r++) {
        int j = lane + r * 32;
        int h = j >> 3;
        float S1 = s1[h] / fmaxf(den[h], 1e-16f);
        float o = fmaf(g_aggA[j], S1, fmaf(g_aggC[j], s0, bias1[j]));
        o = o > 0.f ? o : expm1f(o);    // elu
        g_h1[n * 64 + j] = o;
    }
}

// ---------------- layer-2 node transforms: out[n,j] = h1[n,:]@W[:,j] + b[j] ----------------
__global__ void k_lin(const float* __restrict__ W, const float* __restrict__ b,
                      int which, int N)
{
    __shared__ float4 sRow[8 * 16];
    float* out = which ? g_xr2 : g_xl2;
    int tid = threadIdx.x;  // 128
    float wcol[64];
    float bb = b[tid];
    #pragma unroll
    for (int k = 0; k < 64; k++) wcol[k] = W[k * 128 + tid];
    int n0 = blockIdx.x * 64;
    for (int nb = n0; nb < n0 + 64 && nb < N; nb += 8) {
        int rows = min(8, N - nb);
        __syncthreads();
        for (int i = tid; i < rows * 16; i += 128)
            sRow[i] = ((const float4*)g_h1)[nb * 16 + i];
        __syncthreads();
        for (int r = 0; r < rows; r++) {
            float acc = bb;
            #pragma unroll
            for (int k4 = 0; k4 < 16; k4++) {
                float4 rv = sRow[r * 16 + k4];
                acc = fmaf(rv.x, wcol[4 * k4 + 0], acc);
                acc = fmaf(rv.y, wcol[4 * k4 + 1], acc);
                acc = fmaf(rv.z, wcol[4 * k4 + 2], acc);
                acc = fmaf(rv.w, wcol[4 * k4 + 3], acc);
            }
            out[(size_t)(nb + r) * 128 + tid] = acc;
        }
    }
}

// ---------------- layer 2 attention + final projection consts: warp per dst node ----------------
__global__ void k_attn2(const float* __restrict__ ea, const float* __restrict__ att2,
                        const float* __restrict__ bias2, const float* __restrict__ Wd,
                        int N)
{
    __shared__ float su[128], sv[128], sat[128], sb2[128], swd[256];
    int tid = threadIdx.x;  // 256
    if (tid < 128) { su[tid] = g_u2[tid]; sv[tid] = g_v2[tid]; sat[tid] = att2[tid]; sb2[tid] = bias2[tid]; }
    if (tid < 256) swd[tid] = Wd[tid];
    __syncthreads();
    int warp = tid >> 5, lane = tid & 31;
    int n = blockIdx.x * 8 + warp;
    if (n >= N) return;
    int beg = g_rowptr[n], end = g_rowptr[n + 1];

    float xr[4], u[4], v[4], at[4];
    #pragma unroll
    for (int k = 0; k < 4; k++) {
        int ch = lane + 32 * k;
        xr[k] = g_xr2[(size_t)n * 128 + ch];
        u[k] = su[ch]; v[k] = sv[ch]; at[k] = sat[ch];
    }

    // pass 1: max score
    float mx = -1e30f;
    for (int ei = beg; ei < end; ei++) {
        int e = g_elist[ei];
        const float* xl = &g_xl2[(size_t)g_src[e] * 128];
        float a = ea[e];
        float sc = 0.f;
        #pragma unroll
        for (int k = 0; k < 4; k++) {
            float m = xl[lane + 32 * k] + xr[k] + fmaf(a, u[k], v[k]);
            m = m > 0.f ? m : 0.2f * m;
            sc = fmaf(m, at[k], sc);
        }
        #pragma unroll
        for (int off = 16; off; off >>= 1) sc += __shfl_xor_sync(0xffffffffu, sc, off);
        mx = fmaxf(mx, sc);
    }

    // pass 2: recompute score, exp-weighted accumulate xl2[src]
    float den = 0.f;
    float acc[4] = {0.f, 0.f, 0.f, 0.f};
    for (int ei = beg; ei < end; ei++) {
        int e = g_elist[ei];
        const float* xl = &g_xl2[(size_t)g_src[e] * 128];
        float a = ea[e];
        float xlv[4];
        float sc = 0.f;
        #pragma unroll
        for (int k = 0; k < 4; k++) {
            xlv[k] = xl[lane + 32 * k];
            float m = xlv[k] + xr[k] + fmaf(a, u[k], v[k]);
            m = m > 0.f ? m : 0.2f * m;
            sc = fmaf(m, at[k], sc);
        }
        #pragma unroll
        for (int off = 16; off; off >>= 1) sc += __shfl_xor_sync(0xffffffffu, sc, off);
        float ex = __expf(sc - mx);
        den += ex;
        #pragma unroll
        for (int k = 0; k < 4; k++) acc[k] = fmaf(ex, xlv[k], acc[k]);
    }
    den = fmaxf(den, 1e-16f);

    float p = 0.f, q = 0.f;
    #pragma unroll
    for (int k = 0; k < 4; k++) {
        int ch = lane + 32 * k;
        float h2 = acc[k] / den + sb2[ch];
        p = fmaf(h2, swd[ch], p);
        q = fmaf(h2, swd[128 + ch], q);
    }
    #pragma unroll
    for (int off = 16; off; off >>= 1) {
        p += __shfl_xor_sync(0xffffffffu, p, off);
        q += __shfl_xor_sync(0xffffffffu, q, off);
    }
    if (lane == 0) { g_p[n] = p; g_q[n] = q; }
}

// ---------------- final edge output ----------------
__global__ void k_final(const float* __restrict__ bd, float* __restrict__ out, int E) {
    int e = blockIdx.x * blockDim.x + threadIdx.x;
    if (e >= E) return;
    out[e] = g_p[g_src[e]] + g_q[g_dst[e]] + bd[0];
}

// ---------------- launch ----------------
extern "C" void kernel_launch(void* const* d_in, const int* in_sizes, int n_in,
                              void* d_out, int out_size)
{
    const float* x     = (const float*)d_in[0];
    const void*  ei    = d_in[1];                 // int64 or int32, detected on device
    const float* ea    = (const float*)d_in[2];
    const float* W_em  = (const float*)d_in[3];
    const float* b_em  = (const float*)d_in[4];
    const float* W0    = (const float*)d_in[5];
    const float* b0    = (const float*)d_in[6];
    const float* Wl1   = (const float*)d_in[7];
    const float* bl1   = (const float*)d_in[8];
    const float* Wr1   = (const float*)d_in[9];
    const float* br1   = (const float*)d_in[10];
    const float* We1   = (const float*)d_in[11];
    const float* att1  = (const float*)d_in[12];
    const float* bias1 = (const float*)d_in[13];
    const float* Wl2   = (const float*)d_in[14];
    const float* bl2   = (const float*)d_in[15];
    const float* Wr2   = (const float*)d_in[16];
    const float* br2   = (const float*)d_in[17];
    const float* We2   = (const float*)d_in[18];
    const float* att2  = (const float*)d_in[19];
    const float* bias2 = (const float*)d_in[20];
    const float* Wd    = (const float*)d_in[21];
    const float* bd    = (const float*)d_in[22];
    float* out = (float*)d_out;

    int N = in_sizes[0];   // x is [N,1]
    int E = in_sizes[2];   // edge_attr is [E,1]

    k_pre<<<1, 128>>>(W_em, b_em, W0, b0, Wl1, bl1, Wr1, br1, We1, We2, ei);
    k_zero<<<(N + 255) / 256, 256>>>(N);
    k_convert<<<(E + 255) / 256, 256>>>(ei, E);
    k_scan<<<1, 1024>>>(N);
    k_zero<<<(N + 255) / 256, 256>>>(N);
    k_scatter<<<(E + 255) / 256, 256>>>(E);
    k_layer1<<<(N + 7) / 8, 256>>>(x, ea, att1, bias1, N);
    k_lin<<<(N + 63) / 64, 128>>>(Wl2, bl2, 0, N);
    k_lin<<<(N + 63) / 64, 128>>>(Wr2, br2, 1, N);
    k_attn2<<<(N + 7) / 8, 256>>>(ea, att2, bias2, Wd, N);
    k_final<<<(E + 255) / 256, 256>>>(bd, out, E);
}

// round 3
// speedup vs baseline: 1.4723x; 1.4723x over previous
#include <cuda_runtime.h>
#include <cuda_bf16.h>
#include <math.h>

#define MAXN 50000
#define MAXE 800000

// ---------------- scratch (device globals; no allocation allowed) ----------------
__device__ int   g_is64;
__device__ int   g_src[MAXE];          // original order (for final kernel)
__device__ int   g_dst[MAXE];
__device__ int   g_rowptr[MAXN + 1];
__device__ int   g_cursor[MAXN];
__device__ int   g_srcs[MAXE];         // src sorted by dst (CSR payload)
__device__ float g_eas[MAXE];          // edge_attr sorted by dst
__device__ __align__(16) float g_h1[MAXN * 64];
__device__ __align__(16) float g_xl2[(size_t)MAXN * 128];
__device__ __align__(16) float g_xr2[(size_t)MAXN * 128];
__device__ float g_p[MAXN];
__device__ float g_q[MAXN];
// layer-1 folded constants: float4(cS, cD, cE, cC) per channel j (j = h*8+c)
__device__ __align__(16) float4 g_cpack[64];
__device__ float g_aggA[64];   // = W0@Wl1 (source-side coefficient)
__device__ float g_aggC[64];   // = b0@Wl1 + bl1 (source-side constant)
// layer-2 folded edge-embedding: ee2 = a*u2 + v2
__device__ float g_u2[128];
__device__ float g_v2[128];

// ---------------- tiny precompute + int64 detection ----------------
__global__ void k_pre(const float* __restrict__ W_em, const float* __restrict__ b_em,
                      const float* __restrict__ W0,   const float* __restrict__ b0,
                      const float* __restrict__ Wl1,  const float* __restrict__ bl1,
                      const float* __restrict__ Wr1,  const float* __restrict__ br1,
                      const float* __restrict__ We1,  const float* __restrict__ We2,
                      const void* __restrict__ ei)
{
    int t = threadIdx.x;
    if (t == 0) {
        const long long* p = (const long long*)ei;
        int is64 = 1;
        for (int i = 0; i < 8; i++) {
            long long v = p[i];
            if (v < 0 || v >= (1LL << 31)) { is64 = 0; break; }
        }
        g_is64 = is64;
    }
    if (t < 64) {
        float cS = 0.f, cD = 0.f, cE = 0.f;
        float Cl = bl1[t], Cr = br1[t], v1 = 0.f;
        for (int k = 0; k < 128; k++) {
            float wl = Wl1[k * 64 + t];
            float wr = Wr1[k * 64 + t];
            float we = We1[k * 64 + t];
            cS += W0[k]   * wl;
            cD += W0[k]   * wr;
            cE += W_em[k] * we;
            Cl += b0[k]   * wl;
            Cr += b0[k]   * wr;
            v1 += b_em[k] * we;
        }
        g_cpack[t] = make_float4(cS, cD, cE, Cl + Cr + v1);
        g_aggA[t] = cS;
        g_aggC[t] = Cl;
    }
    if (t < 128) {
        float u = 0.f, v = 0.f;
        for (int k = 0; k < 128; k++) {
            float w = We2[k * 128 + t];
            u += W_em[k] * w;
            v += b_em[k] * w;
        }
        g_u2[t] = u;
        g_v2[t] = v;
    }
}

// ---------------- CSR build ----------------
__global__ void k_zero(int n) {
    int i = blockIdx.x * blockDim.x + threadIdx.x;
    if (i < n) g_cursor[i] = 0;
}

__global__ void k_convert(const void* __restrict__ ei, int E) {
    int e = blockIdx.x * blockDim.x + threadIdx.x;
    if (e >= E) return;
    int s, d;
    if (g_is64) {
        const long long* p = (const long long*)ei;
        s = (int)__ldg(&p[e]); d = (int)__ldg(&p[E + e]);
    } else {
        const int* p = (const int*)ei;
        s = __ldg(&p[e]); d = __ldg(&p[E + e]);
    }
    g_src[e] = s;
    g_dst[e] = d;
    atomicAdd(&g_cursor[d], 1);
}

// single-block scan: each thread owns a contiguous chunk. Writes rowptr AND
// re-primes cursor with the same prefix (so scatter needs no second zero pass).
__global__ void k_scan(int n) {
    __shared__ int ws[32];
    int tid = threadIdx.x;                   // 1024
    int lane = tid & 31, w = tid >> 5;
    int chunk = (n + 1023) >> 10;
    int beg = tid * chunk;
    int end = min(beg + chunk, n);

    int sum = 0;
    for (int i = beg; i < end; i++) sum += g_cursor[i];

    // block-wide exclusive scan of thread sums
    int incl = sum;
    #pragma unroll
    for (int off = 1; off < 32; off <<= 1) {
        int t = __shfl_up_sync(0xffffffffu, incl, off);
        if (lane >= off) incl += t;
    }
    if (lane == 31) ws[w] = incl;
    __syncthreads();
    if (w == 0) {
        int y = ws[lane];
        #pragma unroll
        for (int off = 1; off < 32; off <<= 1) {
            int t = __shfl_up_sync(0xffffffffu, y, off);
            if (lane >= off) y += t;
        }
        ws[lane] = y;
    }
    __syncthreads();
    int run = incl - sum + (w > 0 ? ws[w - 1] : 0);   // exclusive prefix

    for (int i = beg; i < end; i++) {
        int v = g_cursor[i];
        g_rowptr[i] = run;
        g_cursor[i] = run;
        run += v;
    }
    if (tid == 1023) g_rowptr[n] = run;
}

__global__ void k_scatter(const float* __restrict__ ea, int E) {
    int e = blockIdx.x * blockDim.x + threadIdx.x;
    if (e >= E) return;
    int d = g_dst[e];
    int pos = atomicAdd(&g_cursor[d], 1);
    g_srcs[pos] = g_src[e];
    g_eas[pos]  = ea[e];
}

// ---------------- layer 1: warp per dst node, single-pass online softmax ----------------
__global__ void k_layer1(const float* __restrict__ x,
                         const float* __restrict__ att1, const float* __restrict__ bias1,
                         int N)
{
    __shared__ float4 sc[64];
    __shared__ float  sa[64];
    int tid = threadIdx.x;
    if (tid < 64) { sc[tid] = g_cpack[tid]; sa[tid] = att1[tid]; }
    __syncthreads();
    int warp = tid >> 5, lane = tid & 31;
    int n = blockIdx.x * 8 + warp;
    if (n >= N) return;
    int beg = g_rowptr[n], end = g_rowptr[n + 1];
    float xd = x[n];

    float mx[8], den[8], s1[8];
    #pragma unroll
    for (int h = 0; h < 8; h++) { mx[h] = -1e30f; den[h] = 0.f; s1[h] = 0.f; }

    for (int ei = beg + lane; ei < end; ei += 32) {
        float xs = x[g_srcs[ei]];
        float a  = g_eas[ei];
        #pragma unroll
        for (int h = 0; h < 8; h++) {
            float scv = 0.f;
            #pragma unroll
            for (int c = 0; c < 8; c++) {
                int j = h * 8 + c;
                float4 q = sc[j];
                float m = fmaf(q.x, xs, fmaf(q.y, xd, fmaf(q.z, a, q.w)));
                m = m > 0.f ? m : 0.2f * m;
                scv = fmaf(m, sa[j], scv);
            }
            float mnew = fmaxf(mx[h], scv);
            float corr = __expf(mx[h] - mnew);
            float ex   = __expf(scv - mnew);
            den[h] = fmaf(den[h], corr, ex);
            s1[h]  = fmaf(s1[h],  corr, ex * xs);
            mx[h] = mnew;
        }
    }
    // combine lanes: rescale by global max
    #pragma unroll
    for (int h = 0; h < 8; h++) {
        float M = mx[h];
        #pragma unroll
        for (int off = 16; off; off >>= 1)
            M = fmaxf(M, __shfl_xor_sync(0xffffffffu, M, off));
        float corr = __expf(mx[h] - M);
        float d2 = den[h] * corr;
        float s2 = s1[h]  * corr;
        #pragma unroll
        for (int off = 16; off; off >>= 1) {
            d2 += __shfl_xor_sync(0xffffffffu, d2, off);
            s2 += __shfl_xor_sync(0xffffffffu, s2, off);
        }
        den[h] = d2; s1[h] = s2;
    }

    float s0 = (end > beg) ? 1.f : 0.f;
    #pragma unroll
    for (int r = 0; r < 2; r++) {
        int j = lane + r * 32;
        int h = j >> 3;
        float S1 = s1[h] / fmaxf(den[h], 1e-16f);
        float o = fmaf(g_aggA[j], S1, fmaf(g_aggC[j], s0, bias1[j]));
        o = o > 0.f ? o : expm1f(o);    // elu
        g_h1[n * 64 + j] = o;
    }
}

// ---------------- layer-2 node transforms (both matrices in one kernel) ----------------
__global__ void k_lin2(const float* __restrict__ Wl, const float* __restrict__ bl,
                       const float* __restrict__ Wr, const float* __restrict__ br,
                       int N)
{
    __shared__ float4 sRow[8 * 16];
    int tid = threadIdx.x;                 // 256
    int half = tid >> 7;                   // 0 -> xl2, 1 -> xr2
    int col  = tid & 127;
    const float* W = half ? Wr : Wl;
    const float* b = half ? br : bl;
    float* out = half ? g_xr2 : g_xl2;

    float wcol[64];
    float bb = b[col];
    #pragma unroll
    for (int k = 0; k < 64; k++) wcol[k] = W[k * 128 + col];

    int n0 = blockIdx.x * 64;
    for (int nb = n0; nb < n0 + 64 && nb < N; nb += 8) {
        int rows = min(8, N - nb);
        __syncthreads();
        for (int i = tid; i < rows * 16; i += 256)
            sRow[i] = ((const float4*)g_h1)[nb * 16 + i];
        __syncthreads();
        for (int r = 0; r < rows; r++) {
            float acc = bb;
            #pragma unroll
            for (int k4 = 0; k4 < 16; k4++) {
                float4 rv = sRow[r * 16 + k4];
                acc = fmaf(rv.x, wcol[4 * k4 + 0], acc);
                acc = fmaf(rv.y, wcol[4 * k4 + 1], acc);
                acc = fmaf(rv.z, wcol[4 * k4 + 2], acc);
                acc = fmaf(rv.w, wcol[4 * k4 + 3], acc);
            }
            out[(size_t)(nb + r) * 128 + col] = acc;
        }
    }
}

// ---------------- layer 2 attention, single-pass online softmax ----------------
__global__ void k_attn2(const float* __restrict__ att2,
                        const float* __restrict__ bias2, const float* __restrict__ Wd,
                        int N)
{
    __shared__ float su[128], sv[128], sat[128], sb2[128], swd[256];
    int tid = threadIdx.x;  // 256
    if (tid < 128) { su[tid] = g_u2[tid]; sv[tid] = g_v2[tid]; sat[tid] = att2[tid]; sb2[tid] = bias2[tid]; }
    if (tid < 256) swd[tid] = Wd[tid];
    __syncthreads();
    int warp = tid >> 5, lane = tid & 31;
    int n = blockIdx.x * 8 + warp;
    if (n >= N) return;
    int beg = g_rowptr[n], end = g_rowptr[n + 1];

    float xr[4], u[4], v[4], at[4];
    #pragma unroll
    for (int k = 0; k < 4; k++) {
        int ch = lane + 32 * k;
        xr[k] = g_xr2[(size_t)n * 128 + ch];
        u[k] = su[ch]; v[k] = sv[ch]; at[k] = sat[ch];
    }

    float mx = -1e30f, den = 0.f;
    float acc[4] = {0.f, 0.f, 0.f, 0.f};
    for (int ei = beg; ei < end; ei++) {
        int s = g_srcs[ei];
        float a = g_eas[ei];
        const float* xl = &g_xl2[(size_t)s * 128];
        float xlv[4];
        float sc = 0.f;
        #pragma unroll
        for (int k = 0; k < 4; k++) {
            xlv[k] = xl[lane + 32 * k];
            float m = xlv[k] + xr[k] + fmaf(a, u[k], v[k]);
            m = m > 0.f ? m : 0.2f * m;
            sc = fmaf(m, at[k], sc);
        }
        #pragma unroll
        for (int off = 16; off; off >>= 1) sc += __shfl_xor_sync(0xffffffffu, sc, off);
        float mnew = fmaxf(mx, sc);
        float corr = __expf(mx - mnew);
        float ex   = __expf(sc - mnew);
        den = fmaf(den, corr, ex);
        #pragma unroll
        for (int k = 0; k < 4; k++) acc[k] = fmaf(acc[k], corr, ex * xlv[k]);
        mx = mnew;
    }
    den = fmaxf(den, 1e-16f);

    float p = 0.f, q = 0.f;
    #pragma unroll
    for (int k = 0; k < 4; k++) {
        int ch = lane + 32 * k;
        float h2 = acc[k] / den + sb2[ch];
        p = fmaf(h2, swd[ch], p);
        q = fmaf(h2, swd[128 + ch], q);
    }
    #pragma unroll
    for (int off = 16; off; off >>= 1) {
        p += __shfl_xor_sync(0xffffffffu, p, off);
        q += __shfl_xor_sync(0xffffffffu, q, off);
    }
    if (lane == 0) { g_p[n] = p; g_q[n] = q; }
}

// ---------------- final edge output ----------------
__global__ void k_final(const float* __restrict__ bd, float* __restrict__ out, int E) {
    int e = blockIdx.x * blockDim.x + threadIdx.x;
    if (e >= E) return;
    out[e] = g_p[g_src[e]] + g_q[g_dst[e]] + bd[0];
}

// ---------------- launch ----------------
extern "C" void kernel_launch(void* const* d_in, const int* in_sizes, int n_in,
                              void* d_out, int out_size)
{
    const float* x     = (const float*)d_in[0];
    const void*  ei    = d_in[1];                 // int64 or int32, detected on device
    const float* ea    = (const float*)d_in[2];
    const float* W_em  = (const float*)d_in[3];
    const float* b_em  = (const float*)d_in[4];
    const float* W0    = (const float*)d_in[5];
    const float* b0    = (const float*)d_in[6];
    const float* Wl1   = (const float*)d_in[7];
    const float* bl1   = (const float*)d_in[8];
    const float* Wr1   = (const float*)d_in[9];
    const float* br1   = (const float*)d_in[10];
    const float* We1   = (const float*)d_in[11];
    const float* att1  = (const float*)d_in[12];
    const float* bias1 = (const float*)d_in[13];
    const float* Wl2   = (const float*)d_in[14];
    const float* bl2   = (const float*)d_in[15];
    const float* Wr2   = (const float*)d_in[16];
    const float* br2   = (const float*)d_in[17];
    const float* We2   = (const float*)d_in[18];
    const float* att2  = (const float*)d_in[19];
    const float* bias2 = (const float*)d_in[20];
    const float* Wd    = (const float*)d_in[21];
    const float* bd    = (const float*)d_in[22];
    float* out = (float*)d_out;

    int N = in_sizes[0];   // x is [N,1]
    int E = in_sizes[2];   // edge_attr is [E,1]

    k_pre<<<1, 128>>>(W_em, b_em, W0, b0, Wl1, bl1, Wr1, br1, We1, We2, ei);
    k_zero<<<(N + 255) / 256, 256>>>(N);
    k_convert<<<(E + 255) / 256, 256>>>(ei, E);
    k_scan<<<1, 1024>>>(N);
    k_scatter<<<(E + 255) / 256, 256>>>(ea, E);
    k_layer1<<<(N + 7) / 8, 256>>>(x, att1, bias1, N);
    k_lin2<<<(N + 63) / 64, 256>>>(Wl2, bl2, Wr2, br2, N);
    k_attn2<<<(N + 7) / 8, 256>>>(att2, bias2, Wd, N);
    k_final<<<(E + 255) / 256, 256>>>(bd, out, E);
}

// round 4
// speedup vs baseline: 1.6744x; 1.1373x over previous
#include <cuda_runtime.h>
#include <cuda_bf16.h>
#include <math.h>

#define MAXN 50000
#define MAXE 800000
#define SCAN_TILE 4096
#define MAX_BLKS ((MAXN + SCAN_TILE - 1) / SCAN_TILE + 1)

// ---------------- scratch (device globals; no allocation allowed) ----------------
__device__ int   g_is64;
__device__ int   g_src[MAXE];          // original order (for final kernel)
__device__ int   g_dst[MAXE];
__device__ int   g_rowptr[MAXN + 1];
__device__ int   g_cursor[MAXN];
__device__ int2  g_pair[MAXE];         // (src, ea-bits) sorted by dst
__device__ int   g_bsum[MAX_BLKS];
__device__ int   g_boff[MAX_BLKS];
__device__ __align__(16) float g_h1[MAXN * 64];
__device__ __align__(16) float g_xl2[(size_t)MAXN * 128];
__device__ __align__(16) float g_xr2[(size_t)MAXN * 128];
__device__ float g_p[MAXN];
__device__ float g_q[MAXN];
// layer-1 folded constants: float4(cS, cD, cE, cC) per channel j (j = h*8+c)
__device__ __align__(16) float4 g_cpack[64];
__device__ float g_aggA[64];   // = W0@Wl1 (source-side coefficient)
__device__ float g_aggC[64];   // = b0@Wl1 + bl1 (source-side constant)
// layer-2 folded edge-embedding: ee2 = a*u2 + v2
__device__ float g_u2[128];
__device__ float g_v2[128];

// ---------------- tiny precompute + int64 detection ----------------
__global__ void k_pre(const float* __restrict__ W_em, const float* __restrict__ b_em,
                      const float* __restrict__ W0,   const float* __restrict__ b0,
                      const float* __restrict__ Wl1,  const float* __restrict__ bl1,
                      const float* __restrict__ Wr1,  const float* __restrict__ br1,
                      const float* __restrict__ We1,  const float* __restrict__ We2,
                      const void* __restrict__ ei)
{
    int t = threadIdx.x;
    if (t == 0) {
        const long long* p = (const long long*)ei;
        int is64 = 1;
        for (int i = 0; i < 8; i++) {
            long long v = p[i];
            if (v < 0 || v >= (1LL << 31)) { is64 = 0; break; }
        }
        g_is64 = is64;
    }
    if (t < 64) {
        float cS = 0.f, cD = 0.f, cE = 0.f;
        float Cl = bl1[t], Cr = br1[t], v1 = 0.f;
        for (int k = 0; k < 128; k++) {
            float wl = Wl1[k * 64 + t];
            float wr = Wr1[k * 64 + t];
            float we = We1[k * 64 + t];
            cS += W0[k]   * wl;
            cD += W0[k]   * wr;
            cE += W_em[k] * we;
            Cl += b0[k]   * wl;
            Cr += b0[k]   * wr;
            v1 += b_em[k] * we;
        }
        g_cpack[t] = make_float4(cS, cD, cE, Cl + Cr + v1);
        g_aggA[t] = cS;
        g_aggC[t] = Cl;
    }
    if (t < 128) {
        float u = 0.f, v = 0.f;
        for (int k = 0; k < 128; k++) {
            float w = We2[k * 128 + t];
            u += W_em[k] * w;
            v += b_em[k] * w;
        }
        g_u2[t] = u;
        g_v2[t] = v;
    }
}

// ---------------- CSR build ----------------
__global__ void k_zero(int n) {
    int i = blockIdx.x * blockDim.x + threadIdx.x;
    if (i < n) g_cursor[i] = 0;
}

__global__ void k_convert(const void* __restrict__ ei, int E) {
    int e = blockIdx.x * blockDim.x + threadIdx.x;
    if (e >= E) return;
    int s, d;
    if (g_is64) {
        const long long* p = (const long long*)ei;
        s = (int)__ldg(&p[e]); d = (int)__ldg(&p[E + e]);
    } else {
        const int* p = (const int*)ei;
        s = __ldg(&p[e]); d = __ldg(&p[E + e]);
    }
    g_src[e] = s;
    g_dst[e] = d;
    atomicAdd(&g_cursor[d], 1);
}

// ---------------- parallel scan: per-block sums, scan sums, rescan ----------------
__global__ void k_bsum(int n) {
    __shared__ int ws[32];
    int tid = threadIdx.x;                       // 1024
    int base = blockIdx.x * SCAN_TILE;
    int sum = 0;
    #pragma unroll
    for (int k = 0; k < 4; k++) {
        int i = base + tid + k * 1024;
        if (i < n) sum += g_cursor[i];
    }
    int lane = tid & 31, w = tid >> 5;
    #pragma unroll
    for (int off = 16; off; off >>= 1) sum += __shfl_xor_sync(0xffffffffu, sum, off);
    if (lane == 0) ws[w] = sum;
    __syncthreads();
    if (w == 0) {
        int v = ws[lane];
        #pragma unroll
        for (int off = 16; off; off >>= 1) v += __shfl_xor_sync(0xffffffffu, v, off);
        if (lane == 0) g_bsum[blockIdx.x] = v;
    }
}

__global__ void k_bscan(int nb) {                // 1 warp, nb <= 32
    int lane = threadIdx.x;
    int v = (lane < nb) ? g_bsum[lane] : 0;
    int incl = v;
    #pragma unroll
    for (int off = 1; off < 32; off <<= 1) {
        int t = __shfl_up_sync(0xffffffffu, incl, off);
        if (lane >= off) incl += t;
    }
    if (lane < nb) g_boff[lane] = incl - v;
    if (lane == nb - 1) g_rowptr[0] = 0;         // placeholder; real total written by k_scan2
}

__global__ void k_scan2(int n) {
    __shared__ int s[SCAN_TILE];
    __shared__ int ws[32];
    int tid = threadIdx.x;                        // 1024
    int base = blockIdx.x * SCAN_TILE;
    #pragma unroll
    for (int k = 0; k < 4; k++) {
        int i = base + tid + k * 1024;
        s[tid + k * 1024] = (i < n) ? g_cursor[i] : 0;
    }
    __syncthreads();
    int a0 = s[4 * tid], a1 = s[4 * tid + 1], a2 = s[4 * tid + 2], a3 = s[4 * tid + 3];
    int tsum = a0 + a1 + a2 + a3;
    int lane = tid & 31, w = tid >> 5;
    int incl = tsum;
    #pragma unroll
    for (int off = 1; off < 32; off <<= 1) {
        int t = __shfl_up_sync(0xffffffffu, incl, off);
        if (lane >= off) incl += t;
    }
    if (lane == 31) ws[w] = incl;
    __syncthreads();
    if (w == 0) {
        int y = ws[lane];
        #pragma unroll
        for (int off = 1; off < 32; off <<= 1) {
            int t = __shfl_up_sync(0xffffffffu, y, off);
            if (lane >= off) y += t;
        }
        ws[lane] = y;
    }
    __syncthreads();
    int run = g_boff[blockIdx.x] + incl - tsum + (w > 0 ? ws[w - 1] : 0);
    // write prefixes for the 4 owned elements
    int pref[4] = {run, run + a0, run + a0 + a1, run + a0 + a1 + a2};
    #pragma unroll
    for (int k = 0; k < 4; k++) {
        int i = base + 4 * tid + k;
        if (i < n) { g_rowptr[i] = pref[k]; g_cursor[i] = pref[k]; }
        if (i == n - 1) g_rowptr[n] = pref[k] + ((k == 3) ? a3 : (k == 2) ? a2 : (k == 1) ? a1 : a0);
    }
}

__global__ void k_scatter(const float* __restrict__ ea, int E) {
    int e = blockIdx.x * blockDim.x + threadIdx.x;
    if (e >= E) return;
    int d = g_dst[e];
    int pos = atomicAdd(&g_cursor[d], 1);
    g_pair[pos] = make_int2(g_src[e], __float_as_int(ea[e]));
}

// ---------------- layer 1: warp per dst node, single-pass online softmax ----------------
__global__ void k_layer1(const float* __restrict__ x,
                         const float* __restrict__ att1, const float* __restrict__ bias1,
                         int N)
{
    __shared__ float4 sc[64];
    __shared__ float  sa[64];
    int tid = threadIdx.x;
    if (tid < 64) { sc[tid] = g_cpack[tid]; sa[tid] = att1[tid]; }
    __syncthreads();
    int warp = tid >> 5, lane = tid & 31;
    int n = blockIdx.x * 8 + warp;
    if (n >= N) return;
    int beg = g_rowptr[n], end = g_rowptr[n + 1];
    float xd = x[n];

    float mx[8], den[8], s1[8];
    #pragma unroll
    for (int h = 0; h < 8; h++) { mx[h] = -1e30f; den[h] = 0.f; s1[h] = 0.f; }

    for (int ei = beg + lane; ei < end; ei += 32) {
        int2 pr = g_pair[ei];
        float xs = x[pr.x];
        float a  = __int_as_float(pr.y);
        #pragma unroll
        for (int h = 0; h < 8; h++) {
            float scv = 0.f;
            #pragma unroll
            for (int c = 0; c < 8; c++) {
                int j = h * 8 + c;
                float4 q = sc[j];
                float m = fmaf(q.x, xs, fmaf(q.y, xd, fmaf(q.z, a, q.w)));
                m = m > 0.f ? m : 0.2f * m;
                scv = fmaf(m, sa[j], scv);
            }
            float mnew = fmaxf(mx[h], scv);
            float corr = __expf(mx[h] - mnew);
            float ex   = __expf(scv - mnew);
            den[h] = fmaf(den[h], corr, ex);
            s1[h]  = fmaf(s1[h],  corr, ex * xs);
            mx[h] = mnew;
        }
    }
    // combine lanes: rescale by global max
    #pragma unroll
    for (int h = 0; h < 8; h++) {
        float M = mx[h];
        #pragma unroll
        for (int off = 16; off; off >>= 1)
            M = fmaxf(M, __shfl_xor_sync(0xffffffffu, M, off));
        float corr = __expf(mx[h] - M);
        float d2 = den[h] * corr;
        float s2 = s1[h]  * corr;
        #pragma unroll
        for (int off = 16; off; off >>= 1) {
            d2 += __shfl_xor_sync(0xffffffffu, d2, off);
            s2 += __shfl_xor_sync(0xffffffffu, s2, off);
        }
        den[h] = d2; s1[h] = s2;
    }

    float s0 = (end > beg) ? 1.f : 0.f;
    #pragma unroll
    for (int r = 0; r < 2; r++) {
        int j = lane + r * 32;
        int h = j >> 3;
        float S1 = s1[h] / fmaxf(den[h], 1e-16f);
        float o = fmaf(g_aggA[j], S1, fmaf(g_aggC[j], s0, bias1[j]));
        o = o > 0.f ? o : expm1f(o);    // elu
        g_h1[n * 64 + j] = o;
    }
}

// ---------------- layer-2 node transforms (both matrices in one kernel) ----------------
__global__ void k_lin2(const float* __restrict__ Wl, const float* __restrict__ bl,
                       const float* __restrict__ Wr, const float* __restrict__ br,
                       int N)
{
    __shared__ float4 sRow[8 * 16];
    int tid = threadIdx.x;                 // 256
    int half = tid >> 7;                   // 0 -> xl2, 1 -> xr2
    int col  = tid & 127;
    const float* W = half ? Wr : Wl;
    const float* b = half ? br : bl;
    float* out = half ? g_xr2 : g_xl2;

    float wcol[64];
    float bb = b[col];
    #pragma unroll
    for (int k = 0; k < 64; k++) wcol[k] = W[k * 128 + col];

    int n0 = blockIdx.x * 64;
    for (int nb = n0; nb < n0 + 64 && nb < N; nb += 8) {
        int rows = min(8, N - nb);
        __syncthreads();
        for (int i = tid; i < rows * 16; i += 256)
            sRow[i] = ((const float4*)g_h1)[nb * 16 + i];
        __syncthreads();
        for (int r = 0; r < rows; r++) {
            float acc = bb;
            #pragma unroll
            for (int k4 = 0; k4 < 16; k4++) {
                float4 rv = sRow[r * 16 + k4];
                acc = fmaf(rv.x, wcol[4 * k4 + 0], acc);
                acc = fmaf(rv.y, wcol[4 * k4 + 1], acc);
                acc = fmaf(rv.z, wcol[4 * k4 + 2], acc);
                acc = fmaf(rv.w, wcol[4 * k4 + 3], acc);
            }
            out[(size_t)(nb + r) * 128 + col] = acc;
        }
    }
}

// ---------------- layer 2 attention, batch-4 online softmax ----------------
__global__ void k_attn2(const float* __restrict__ att2,
                        const float* __restrict__ bias2, const float* __restrict__ Wd,
                        int N)
{
    __shared__ float su[128], sv[128], sat[128], sb2[128], swd[256];
    int tid = threadIdx.x;  // 256
    if (tid < 128) { su[tid] = g_u2[tid]; sv[tid] = g_v2[tid]; sat[tid] = att2[tid]; sb2[tid] = bias2[tid]; }
    if (tid < 256) swd[tid] = Wd[tid];
    __syncthreads();
    int warp = tid >> 5, lane = tid & 31;
    int n = blockIdx.x * 8 + warp;
    if (n >= N) return;
    int beg = g_rowptr[n], end = g_rowptr[n + 1];

    float xr[4], u[4], v[4], at[4];
    #pragma unroll
    for (int k = 0; k < 4; k++) {
        int ch = lane + 32 * k;
        xr[k] = g_xr2[(size_t)n * 128 + ch];
        u[k] = su[ch]; v[k] = sv[ch]; at[k] = sat[ch];
    }

    float mx = -1e30f, den = 0.f;
    float acc[4] = {0.f, 0.f, 0.f, 0.f};

    int ei = beg;
    for (; ei + 4 <= end; ei += 4) {
        float sc[4], xlv[4][4];
        #pragma unroll
        for (int j = 0; j < 4; j++) {
            int2 pr = g_pair[ei + j];
            const float* xl = &g_xl2[(size_t)pr.x * 128];
            float a = __int_as_float(pr.y);
            float t = 0.f;
            #pragma unroll
            for (int k = 0; k < 4; k++) {
                float xv = xl[lane + 32 * k];
                xlv[j][k] = xv;
                float m = xv + xr[k] + fmaf(a, u[k], v[k]);
                m = m > 0.f ? m : 0.2f * m;
                t = fmaf(m, at[k], t);
            }
            sc[j] = t;
        }
        // 4 interleaved warp reductions (independent chains)
        #pragma unroll
        for (int off = 16; off; off >>= 1) {
            #pragma unroll
            for (int j = 0; j < 4; j++)
                sc[j] += __shfl_xor_sync(0xffffffffu, sc[j], off);
        }
        float mb = fmaxf(fmaxf(sc[0], sc[1]), fmaxf(sc[2], sc[3]));
        float ex0 = __expf(sc[0] - mb), ex1 = __expf(sc[1] - mb);
        float ex2 = __expf(sc[2] - mb), ex3 = __expf(sc[3] - mb);
        float mnew = fmaxf(mx, mb);
        float corr  = __expf(mx - mnew);
        float scale = __expf(mb - mnew);
        den = fmaf(den, corr, (ex0 + ex1 + ex2 + ex3) * scale);
        #pragma unroll
        for (int k = 0; k < 4; k++) {
            float s = fmaf(ex0, xlv[0][k], fmaf(ex1, xlv[1][k],
                      fmaf(ex2, xlv[2][k], ex3 * xlv[3][k])));
            acc[k] = fmaf(acc[k], corr, s * scale);
        }
        mx = mnew;
    }
    for (; ei < end; ei++) {
        int2 pr = g_pair[ei];
        const float* xl = &g_xl2[(size_t)pr.x * 128];
        float a = __int_as_float(pr.y);
        float xlv[4];
        float sc = 0.f;
        #pragma unroll
        for (int k = 0; k < 4; k++) {
            xlv[k] = xl[lane + 32 * k];
            float m = xlv[k] + xr[k] + fmaf(a, u[k], v[k]);
            m = m > 0.f ? m : 0.2f * m;
            sc = fmaf(m, at[k], sc);
        }
        #pragma unroll
        for (int off = 16; off; off >>= 1) sc += __shfl_xor_sync(0xffffffffu, sc, off);
        float mnew = fmaxf(mx, sc);
        float corr = __expf(mx - mnew);
        float ex   = __expf(sc - mnew);
        den = fmaf(den, corr, ex);
        #pragma unroll
        for (int k = 0; k < 4; k++) acc[k] = fmaf(acc[k], corr, ex * xlv[k]);
        mx = mnew;
    }
    den = fmaxf(den, 1e-16f);

    float p = 0.f, q = 0.f;
    #pragma unroll
    for (int k = 0; k < 4; k++) {
        int ch = lane + 32 * k;
        float h2 = acc[k] / den + sb2[ch];
        p = fmaf(h2, swd[ch], p);
        q = fmaf(h2, swd[128 + ch], q);
    }
    #pragma unroll
    for (int off = 16; off; off >>= 1) {
        p += __shfl_xor_sync(0xffffffffu, p, off);
        q += __shfl_xor_sync(0xffffffffu, q, off);
    }
    if (lane == 0) { g_p[n] = p; g_q[n] = q; }
}

// ---------------- final edge output ----------------
__global__ void k_final(const float* __restrict__ bd, float* __restrict__ out, int E) {
    int e = blockIdx.x * blockDim.x + threadIdx.x;
    if (e >= E) return;
    out[e] = g_p[g_src[e]] + g_q[g_dst[e]] + bd[0];
}

// ---------------- launch ----------------
extern "C" void kernel_launch(void* const* d_in, const int* in_sizes, int n_in,
                              void* d_out, int out_size)
{
    const float* x     = (const float*)d_in[0];
    const void*  ei    = d_in[1];                 // int64 or int32, detected on device
    const float* ea    = (const float*)d_in[2];
    const float* W_em  = (const float*)d_in[3];
    const float* b_em  = (const float*)d_in[4];
    const float* W0    = (const float*)d_in[5];
    const float* b0    = (const float*)d_in[6];
    const float* Wl1   = (const float*)d_in[7];
    const float* bl1   = (const float*)d_in[8];
    const float* Wr1   = (const float*)d_in[9];
    const float* br1   = (const float*)d_in[10];
    const float* We1   = (const float*)d_in[11];
    const float* att1  = (const float*)d_in[12];
    const float* bias1 = (const float*)d_in[13];
    const float* Wl2   = (const float*)d_in[14];
    const float* bl2   = (const float*)d_in[15];
    const float* Wr2   = (const float*)d_in[16];
    const float* br2   = (const float*)d_in[17];
    const float* We2   = (const float*)d_in[18];
    const float* att2  = (const float*)d_in[19];
    const float* bias2 = (const float*)d_in[20];
    const float* Wd    = (const float*)d_in[21];
    const float* bd    = (const float*)d_in[22];
    float* out = (float*)d_out;

    int N = in_sizes[0];   // x is [N,1]
    int E = in_sizes[2];   // edge_attr is [E,1]
    int NB = (N + SCAN_TILE - 1) / SCAN_TILE;

    k_pre<<<1, 128>>>(W_em, b_em, W0, b0, Wl1, bl1, Wr1, br1, We1, We2, ei);
    k_zero<<<(N + 255) / 256, 256>>>(N);
    k_convert<<<(E + 255) / 256, 256>>>(ei, E);
    k_bsum<<<NB, 1024>>>(N);
    k_bscan<<<1, 32>>>(NB);
    k_scan2<<<NB, 1024>>>(N);
    k_scatter<<<(E + 255) / 256, 256>>>(ea, E);
    k_layer1<<<(N + 7) / 8, 256>>>(x, att1, bias1, N);
    k_lin2<<<(N + 63) / 64, 256>>>(Wl2, bl2, Wr2, br2, N);
    k_attn2<<<(N + 7) / 8, 256>>>(att2, bias2, Wd, N);
    k_final<<<(E + 255) / 256, 256>>>(bd, out, E);
}

// round 6
// speedup vs baseline: 2.2491x; 1.3433x over previous
#include <cuda_runtime.h>
#include <cuda_bf16.h>
#include <math.h>

#define MAXN 50000
#define MAXE 800000
#define SCAN_TILE 4096
#define MAX_BLKS ((MAXN + SCAN_TILE - 1) / SCAN_TILE + 1)

// ---------------- scratch (device globals; no allocation allowed) ----------------
__device__ int   g_is64;
__device__ int2  g_sd[MAXE];           // (src, dst) original order
__device__ int   g_rowptr[MAXN + 1];
__device__ int   g_cursor[MAXN];
__device__ int2  g_pair[MAXE];         // (src, ea-bits) sorted by dst
__device__ int   g_bsum[MAX_BLKS];
__device__ __align__(16) float g_h1[MAXN * 64];
__device__ __align__(16) float g_xl2[(size_t)MAXN * 128];
__device__ __align__(16) float g_xr2[(size_t)MAXN * 128];
__device__ float g_p[MAXN];
__device__ float g_q[MAXN];
// layer-1 folded constants: float4(cS, cD, cE, cC) per channel j (j = h*8+c)
__device__ __align__(16) float4 g_cpack[64];
__device__ float g_aggA[64];   // = W0@Wl1 (source-side coefficient)
__device__ float g_aggC[64];   // = b0@Wl1 + bl1 (source-side constant)
// layer-2 folded edge-embedding: ee2 = a*u2 + v2
__device__ float g_u2[128];
__device__ float g_v2[128];

// ---------------- tiny precompute + int64 detection ----------------
__global__ void k_pre(const float* __restrict__ W_em, const float* __restrict__ b_em,
                      const float* __restrict__ W0,   const float* __restrict__ b0,
                      const float* __restrict__ Wl1,  const float* __restrict__ bl1,
                      const float* __restrict__ Wr1,  const float* __restrict__ br1,
                      const float* __restrict__ We1,  const float* __restrict__ We2,
                      const void* __restrict__ ei)
{
    int t = threadIdx.x;
    if (t == 0) {
        const long long* p = (const long long*)ei;
        int is64 = 1;
        for (int i = 0; i < 8; i++) {
            long long v = p[i];
            if (v < 0 || v >= (1LL << 31)) { is64 = 0; break; }
        }
        g_is64 = is64;
    }
    if (t < 64) {
        float cS = 0.f, cD = 0.f, cE = 0.f;
        float Cl = bl1[t], Cr = br1[t], v1 = 0.f;
        for (int k = 0; k < 128; k++) {
            float wl = Wl1[k * 64 + t];
            float wr = Wr1[k * 64 + t];
            float we = We1[k * 64 + t];
            cS += W0[k]   * wl;
            cD += W0[k]   * wr;
            cE += W_em[k] * we;
            Cl += b0[k]   * wl;
            Cr += b0[k]   * wr;
            v1 += b_em[k] * we;
        }
        g_cpack[t] = make_float4(cS, cD, cE, Cl + Cr + v1);
        g_aggA[t] = cS;
        g_aggC[t] = Cl;
    }
    if (t < 128) {
        float u = 0.f, v = 0.f;
        for (int k = 0; k < 128; k++) {
            float w = We2[k * 128 + t];
            u += W_em[k] * w;
            v += b_em[k] * w;
        }
        g_u2[t] = u;
        g_v2[t] = v;
    }
}

// ---------------- CSR build ----------------
__global__ void k_zero(int n) {
    int i = blockIdx.x * blockDim.x + threadIdx.x;
    if (i < n) g_cursor[i] = 0;
}

__global__ void k_convert(const void* __restrict__ ei, int E) {
    int e = blockIdx.x * blockDim.x + threadIdx.x;
    if (e >= E) return;
    int s, d;
    if (g_is64) {
        const long long* p = (const long long*)ei;
        s = (int)__ldg(&p[e]); d = (int)__ldg(&p[E + e]);
    } else {
        const int* p = (const int*)ei;
        s = __ldg(&p[e]); d = __ldg(&p[E + e]);
    }
    g_sd[e] = make_int2(s, d);
    atomicAdd(&g_cursor[d], 1);
}

// ---------------- parallel scan: per-block sums, then rescan (boff computed in-block) ----------------
__global__ void k_bsum(int n) {
    __shared__ int ws[32];
    int tid = threadIdx.x;                       // 1024
    int base = blockIdx.x * SCAN_TILE;
    int sum = 0;
    #pragma unroll
    for (int k = 0; k < 4; k++) {
        int i = base + tid + k * 1024;
        if (i < n) sum += g_cursor[i];
    }
    int lane = tid & 31, w = tid >> 5;
    #pragma unroll
    for (int off = 16; off; off >>= 1) sum += __shfl_xor_sync(0xffffffffu, sum, off);
    if (lane == 0) ws[w] = sum;
    __syncthreads();
    if (w == 0) {
        int v = ws[lane];
        #pragma unroll
        for (int off = 16; off; off >>= 1) v += __shfl_xor_sync(0xffffffffu, v, off);
        if (lane == 0) g_bsum[blockIdx.x] = v;
    }
}

__global__ void k_scan2(int n, int nb) {
    __shared__ int s[SCAN_TILE];
    __shared__ int ws[32];
    __shared__ int s_boff;
    int tid = threadIdx.x;                        // 1024
    int base = blockIdx.x * SCAN_TILE;
    if (tid < 32) {                               // warp 0: block offset from bsum
        int v = (tid < nb && tid < blockIdx.x) ? g_bsum[tid] : 0;
        #pragma unroll
        for (int off = 16; off; off >>= 1) v += __shfl_xor_sync(0xffffffffu, v, off);
        if (tid == 0) s_boff = v;
    }
    #pragma unroll
    for (int k = 0; k < 4; k++) {
        int i = base + tid + k * 1024;
        s[tid + k * 1024] = (i < n) ? g_cursor[i] : 0;
    }
    __syncthreads();
    int a0 = s[4 * tid], a1 = s[4 * tid + 1], a2 = s[4 * tid + 2], a3 = s[4 * tid + 3];
    int tsum = a0 + a1 + a2 + a3;
    int lane = tid & 31, w = tid >> 5;
    int incl = tsum;
    #pragma unroll
    for (int off = 1; off < 32; off <<= 1) {
        int t = __shfl_up_sync(0xffffffffu, incl, off);
        if (lane >= off) incl += t;
    }
    if (lane == 31) ws[w] = incl;
    __syncthreads();
    if (w == 0) {
        int y = ws[lane];
        #pragma unroll
        for (int off = 1; off < 32; off <<= 1) {
            int t = __shfl_up_sync(0xffffffffu, y, off);
            if (lane >= off) y += t;
        }
        ws[lane] = y;
    }
    __syncthreads();
    int run = s_boff + incl - tsum + (w > 0 ? ws[w - 1] : 0);
    int pref[4] = {run, run + a0, run + a0 + a1, run + a0 + a1 + a2};
    int av[4] = {a0, a1, a2, a3};
    #pragma unroll
    for (int k = 0; k < 4; k++) {
        int i = base + 4 * tid + k;
        if (i < n) { g_rowptr[i] = pref[k]; g_cursor[i] = pref[k]; }
        if (i == n - 1) g_rowptr[n] = pref[k] + av[k];
    }
}

__global__ void k_scatter(const float* __restrict__ ea, int E) {
    int e = blockIdx.x * blockDim.x + threadIdx.x;
    if (e >= E) return;
    int2 sd = g_sd[e];
    int pos = atomicAdd(&g_cursor[sd.y], 1);
    g_pair[pos] = make_int2(sd.x, __float_as_int(ea[e]));
}

// ---------------- layer 1: warp per dst node, 2-edge pipelined online softmax ----------------
__global__ void k_layer1(const float* __restrict__ x,
                         const float* __restrict__ att1, const float* __restrict__ bias1,
                         int N)
{
    __shared__ float4 sc[64];
    __shared__ float  sa[64];
    int tid = threadIdx.x;
    if (tid < 64) { sc[tid] = g_cpack[tid]; sa[tid] = att1[tid]; }
    __syncthreads();
    int warp = tid >> 5, lane = tid & 31;
    int n = blockIdx.x * 8 + warp;
    if (n >= N) return;
    int beg = g_rowptr[n], end = g_rowptr[n + 1];
    float xd = x[n];

    float mx[8], den[8], s1[8];
    #pragma unroll
    for (int h = 0; h < 8; h++) { mx[h] = -1e30f; den[h] = 0.f; s1[h] = 0.f; }

    int eix = beg + lane;
    for (; eix + 32 < end; eix += 64) {
        int2 p0 = g_pair[eix], p1 = g_pair[eix + 32];
        float xs0 = x[p0.x], xs1 = x[p1.x];
        float a0 = __int_as_float(p0.y), a1 = __int_as_float(p1.y);
        #pragma unroll
        for (int h = 0; h < 8; h++) {
            float v0 = 0.f, v1 = 0.f;
            #pragma unroll
            for (int c = 0; c < 8; c++) {
                int j = h * 8 + c;
                float4 q = sc[j];
                float m0 = fmaf(q.x, xs0, fmaf(q.y, xd, fmaf(q.z, a0, q.w)));
                float m1 = fmaf(q.x, xs1, fmaf(q.y, xd, fmaf(q.z, a1, q.w)));
                m0 = m0 > 0.f ? m0 : 0.2f * m0;
                m1 = m1 > 0.f ? m1 : 0.2f * m1;
                v0 = fmaf(m0, sa[j], v0);
                v1 = fmaf(m1, sa[j], v1);
            }
            float mb = fmaxf(v0, v1);
            float e0 = __expf(v0 - mb), e1 = __expf(v1 - mb);
            float mnew = fmaxf(mx[h], mb);
            float corr  = __expf(mx[h] - mnew);
            float scale = __expf(mb - mnew);
            den[h] = fmaf(den[h], corr, (e0 + e1) * scale);
            s1[h]  = fmaf(s1[h],  corr, fmaf(e0, xs0, e1 * xs1) * scale);
            mx[h] = mnew;
        }
    }
    if (eix < end) {
        int2 pr = g_pair[eix];
        float xs = x[pr.x];
        float a  = __int_as_float(pr.y);
        #pragma unroll
        for (int h = 0; h < 8; h++) {
            float scv = 0.f;
            #pragma unroll
            for (int c = 0; c < 8; c++) {
                int j = h * 8 + c;
                float4 q = sc[j];
                float m = fmaf(q.x, xs, fmaf(q.y, xd, fmaf(q.z, a, q.w)));
                m = m > 0.f ? m : 0.2f * m;
                scv = fmaf(m, sa[j], scv);
            }
            float mnew = fmaxf(mx[h], scv);
            float corr = __expf(mx[h] - mnew);
            float ex   = __expf(scv - mnew);
            den[h] = fmaf(den[h], corr, ex);
            s1[h]  = fmaf(s1[h],  corr, ex * xs);
            mx[h] = mnew;
        }
    }
    // combine lanes: rescale by global max
    #pragma unroll
    for (int h = 0; h < 8; h++) {
        float M = mx[h];
        #pragma unroll
        for (int off = 16; off; off >>= 1)
            M = fmaxf(M, __shfl_xor_sync(0xffffffffu, M, off));
        float corr = __expf(mx[h] - M);
        float d2 = den[h] * corr;
        float s2 = s1[h]  * corr;
        #pragma unroll
        for (int off = 16; off; off >>= 1) {
            d2 += __shfl_xor_sync(0xffffffffu, d2, off);
            s2 += __shfl_xor_sync(0xffffffffu, s2, off);
        }
        den[h] = d2; s1[h] = s2;
    }

    float s0 = (end > beg) ? 1.f : 0.f;
    #pragma unroll
    for (int r = 0; r < 2; r++) {
        int j = lane + r * 32;
        int h = j >> 3;
        float S1 = s1[h] / fmaxf(den[h], 1e-16f);
        float o = fmaf(g_aggA[j], S1, fmaf(g_aggC[j], s0, bias1[j]));
        o = o > 0.f ? o : expm1f(o);    // elu
        g_h1[n * 64 + j] = o;
    }
}

// ---------------- layer-2 node transforms (both matrices in one kernel) ----------------
__global__ void k_lin2(const float* __restrict__ Wl, const float* __restrict__ bl,
                       const float* __restrict__ Wr, const float* __restrict__ br,
                       int N)
{
    __shared__ float4 sRow[8 * 16];
    int tid = threadIdx.x;                 // 256
    int half = tid >> 7;                   // 0 -> xl2, 1 -> xr2
    int col  = tid & 127;
    const float* W = half ? Wr : Wl;
    const float* b = half ? br : bl;
    float* out = half ? g_xr2 : g_xl2;

    float wcol[64];
    float bb = b[col];
    #pragma unroll
    for (int k = 0; k < 64; k++) wcol[k] = W[k * 128 + col];

    int n0 = blockIdx.x * 64;
    for (int nb = n0; nb < n0 + 64 && nb < N; nb += 8) {
        int rows = min(8, N - nb);
        __syncthreads();
        for (int i = tid; i < rows * 16; i += 256)
            sRow[i] = ((const float4*)g_h1)[nb * 16 + i];
        __syncthreads();
        for (int r = 0; r < rows; r++) {
            float acc = bb;
            #pragma unroll
            for (int k4 = 0; k4 < 16; k4++) {
                float4 rv = sRow[r * 16 + k4];
                acc = fmaf(rv.x, wcol[4 * k4 + 0], acc);
                acc = fmaf(rv.y, wcol[4 * k4 + 1], acc);
                acc = fmaf(rv.z, wcol[4 * k4 + 2], acc);
                acc = fmaf(rv.w, wcol[4 * k4 + 3], acc);
            }
            out[(size_t)(nb + r) * 128 + col] = acc;
        }
    }
}

// ---------------- layer 2 attention: float4 channel layout (ch = 4*lane+k), batch-4 ----------------
__global__ void k_attn2(const float* __restrict__ att2,
                        const float* __restrict__ bias2, const float* __restrict__ Wd,
                        int N)
{
    __shared__ float su[128], sv[128], sat[128], sb2[128], swd[256];
    int tid = threadIdx.x;  // 256
    if (tid < 128) { su[tid] = g_u2[tid]; sv[tid] = g_v2[tid]; sat[tid] = att2[tid]; sb2[tid] = bias2[tid]; }
    if (tid < 256) swd[tid] = Wd[tid];
    __syncthreads();
    int warp = tid >> 5, lane = tid & 31;
    int n = blockIdx.x * 8 + warp;
    if (n >= N) return;
    int beg = g_rowptr[n], end = g_rowptr[n + 1];

    // channel mapping: ch = 4*lane + k  -> one LDG.128 per lane per edge row
    float4 xr = ((const float4*)(&g_xr2[(size_t)n * 128]))[lane];
    float u[4], v[4], at[4];
    #pragma unroll
    for (int k = 0; k < 4; k++) {
        int ch = 4 * lane + k;
        u[k] = su[ch]; v[k] = sv[ch]; at[k] = sat[ch];
    }
    float xrv[4] = {xr.x, xr.y, xr.z, xr.w};

    float mx = -1e30f, den = 0.f;
    float acc[4] = {0.f, 0.f, 0.f, 0.f};

    int ei = beg;
    for (; ei + 4 <= end; ei += 4) {
        float sc[4];
        float4 xlv[4];
        #pragma unroll
        for (int j = 0; j < 4; j++) {
            int2 pr = g_pair[ei + j];
            xlv[j] = ((const float4*)(&g_xl2[(size_t)pr.x * 128]))[lane];
            float a = __int_as_float(pr.y);
            const float* xv = (const float*)&xlv[j];
            float t = 0.f;
            #pragma unroll
            for (int k = 0; k < 4; k++) {
                float m = xv[k] + xrv[k] + fmaf(a, u[k], v[k]);
                m = m > 0.f ? m : 0.2f * m;
                t = fmaf(m, at[k], t);
            }
            sc[j] = t;
        }
        #pragma unroll
        for (int off = 16; off; off >>= 1) {
            #pragma unroll
            for (int j = 0; j < 4; j++)
                sc[j] += __shfl_xor_sync(0xffffffffu, sc[j], off);
        }
        float mb = fmaxf(fmaxf(sc[0], sc[1]), fmaxf(sc[2], sc[3]));
        float ex0 = __expf(sc[0] - mb), ex1 = __expf(sc[1] - mb);
        float ex2 = __expf(sc[2] - mb), ex3 = __expf(sc[3] - mb);
        float mnew = fmaxf(mx, mb);
        float corr  = __expf(mx - mnew);
        float scale = __expf(mb - mnew);
        den = fmaf(den, corr, (ex0 + ex1 + ex2 + ex3) * scale);
        #pragma unroll
        for (int k = 0; k < 4; k++) {
            float s = fmaf(ex0, ((const float*)&xlv[0])[k],
                      fmaf(ex1, ((const float*)&xlv[1])[k],
                      fmaf(ex2, ((const float*)&xlv[2])[k],
                           ex3 * ((const float*)&xlv[3])[k])));
            acc[k] = fmaf(acc[k], corr, s * scale);
        }
        mx = mnew;
    }
    for (; ei < end; ei++) {
        int2 pr = g_pair[ei];
        float4 xl4 = ((const float4*)(&g_xl2[(size_t)pr.x * 128]))[lane];
        const float* xv = (const float*)&xl4;
        float a = __int_as_float(pr.y);
        float sc = 0.f;
        #pragma unroll
        for (int k = 0; k < 4; k++) {
            float m = xv[k] + xrv[k] + fmaf(a, u[k], v[k]);
            m = m > 0.f ? m : 0.2f * m;
            sc = fmaf(m, at[k], sc);
        }
        #pragma unroll
        for (int off = 16; off; off >>= 1) sc += __shfl_xor_sync(0xffffffffu, sc, off);
        float mnew = fmaxf(mx, sc);
        float corr = __expf(mx - mnew);
        float ex   = __expf(sc - mnew);
        den = fmaf(den, corr, ex);
        #pragma unroll
        for (int k = 0; k < 4; k++) acc[k] = fmaf(acc[k], corr, ex * xv[k]);
        mx = mnew;
    }
    den = fmaxf(den, 1e-16f);

    float p = 0.f, q = 0.f;
    #pragma unroll
    for (int k = 0; k < 4; k++) {
        int ch = 4 * lane + k;
        float h2 = acc[k] / den + sb2[ch];
        p = fmaf(h2, swd[ch], p);
        q = fmaf(h2, swd[128 + ch], q);
    }
    #pragma unroll
    for (int off = 16; off; off >>= 1) {
        p += __shfl_xor_sync(0xffffffffu, p, off);
        q += __shfl_xor_sync(0xffffffffu, q, off);
    }
    if (lane == 0) { g_p[n] = p; g_q[n] = q; }
}

// ---------------- final edge output ----------------
__global__ void k_final(const float* __restrict__ bd, float* __restrict__ out, int E) {
    int e = blockIdx.x * blockDim.x + threadIdx.x;
    if (e >= E) return;
    int2 sd = g_sd[e];
    out[e] = g_p[sd.x] + g_q[sd.y] + bd[0];
}

// ---------------- launch ----------------
extern "C" void kernel_launch(void* const* d_in, const int* in_sizes, int n_in,
                              void* d_out, int out_size)
{
    const float* x     = (const float*)d_in[0];
    const void*  ei    = d_in[1];                 // int64 or int32, detected on device
    const float* ea    = (const float*)d_in[2];
    const float* W_em  = (const float*)d_in[3];
    const float* b_em  = (const float*)d_in[4];
    const float* W0    = (const float*)d_in[5];
    const float* b0    = (const float*)d_in[6];
    const float* Wl1   = (const float*)d_in[7];
    const float* bl1   = (const float*)d_in[8];
    const float* Wr1   = (const float*)d_in[9];
    const float* br1   = (const float*)d_in[10];
    const float* We1   = (const float*)d_in[11];
    const float* att1  = (const float*)d_in[12];
    const float* bias1 = (const float*)d_in[13];
    const float* Wl2   = (const float*)d_in[14];
    const float* bl2   = (const float*)d_in[15];
    const float* Wr2   = (const float*)d_in[16];
    const float* br2   = (const float*)d_in[17];
    const float* We2   = (const float*)d_in[18];
    const float* att2  = (const float*)d_in[19];
    const float* bias2 = (const float*)d_in[20];
    const float* Wd    = (const float*)d_in[21];
    const float* bd    = (const float*)d_in[22];
    float* out = (float*)d_out;

    int N = in_sizes[0];   // x is [N,1]
    int E = in_sizes[2];   // edge_attr is [E,1]
    int NB = (N + SCAN_TILE - 1) / SCAN_TILE;

    k_pre<<<1, 128>>>(W_em, b_em, W0, b0, Wl1, bl1, Wr1, br1, We1, We2, ei);
    k_zero<<<(N + 255) / 256, 256>>>(N);
    k_convert<<<(E + 255) / 256, 256>>>(ei, E);
    k_bsum<<<NB, 1024>>>(N);
    k_scan2<<<NB, 1024>>>(N, NB);
    k_scatter<<<(E + 255) / 256, 256>>>(ea, E);
    k_layer1<<<(N + 7) / 8, 256>>>(x, att1, bias1, N);
    k_lin2<<<(N + 63) / 64, 256>>>(Wl2, bl2, Wr2, br2, N);
    k_attn2<<<(N + 7) / 8, 256>>>(att2, bias2, Wd, N);
    k_final<<<(E + 255) / 256, 256>>>(bd, out, E);
}